// round 1
// baseline (speedup 1.0000x reference)
#include <cuda_runtime.h>
#include <cuda_bf16.h>

// Problem constants (fixed by the dataset)
#define BB 32      // batch
#define LL 128     // sequence length
#define TT 63      // tree nodes (2^6 - 1)
#define EE 128     // embedding dim
#define CC 128     // conv/encoder channels
#define HH 256     // GRU hidden
#define GG 768     // 3*H gate columns

// ---------------------------------------------------------------------------
// Device scratch (static allocations only — no cudaMalloc allowed)
// ---------------------------------------------------------------------------
__device__ float d_WcT[EE * CC];          // [e][c]  (Wc transposed)
__device__ float d_WihT0[CC * GG];        // [k][g]  forward  Wih^T
__device__ float d_WihT1[CC * GG];        // [k][g]  backward Wih^T
__device__ float d_enc[BB * LL * CC];     // encoder output (b*L+l, c)
__device__ float d_gi0[(long)BB * LL * GG]; // precomputed input gates, fwd
__device__ float d_gi1[(long)BB * LL * GG]; // precomputed input gates, bwd
__device__ float d_hbuf[2][2][BB * HH];   // [dir][buf][b][k] double-buffered h
__device__ unsigned int d_bar[2];         // per-direction step barrier counters

// ---------------------------------------------------------------------------
// Setup: transpose weights, zero h buffers and barrier counters.
// Runs at the start of every launch (graph replays must be deterministic).
// ---------------------------------------------------------------------------
__global__ void k_setup(const float* __restrict__ Wc,
                        const float* __restrict__ Wih_f,
                        const float* __restrict__ Wih_b)
{
    const int i      = blockIdx.x * blockDim.x + threadIdx.x;
    const int stride = gridDim.x * blockDim.x;

    for (int idx = i; idx < EE * CC; idx += stride) {
        int e = idx / CC, c = idx % CC;
        d_WcT[e * CC + c] = Wc[c * EE + e];
    }
    for (int idx = i; idx < CC * GG; idx += stride) {
        int k = idx / GG, g = idx % GG;
        d_WihT0[idx] = Wih_f[g * CC + k];
        d_WihT1[idx] = Wih_b[g * CC + k];
    }
    for (int idx = i; idx < 2 * 2 * BB * HH; idx += stride) {
        ((float*)d_hbuf)[idx] = 0.f;
    }
    if (i < 2) d_bar[i] = 0u;
}

// ---------------------------------------------------------------------------
// K1: fused tree encoder. One CTA per (b,l).
//   x[t] = Wc @ emb[tok[t]] + bc   (63 projections, shared-memory GEMM)
//   heap accumulate: x[t] += x[2t+1] + x[2t+2]  (t = 30..0)
//   enc = relu(max_t x[t])
// Shared layout (floats):
//   ws  [128][132]  @ 0       (WcT, padded stride 132 -> conflict-free f4)
//   es  [64 ][128]  @ 16896   (gathered embeddings, broadcast reads)
//   xs  [63 ][132]  @ 25088   (node values)
//   bcs [128]       @ 33404
//   tks [64 ] ints  @ 33532
// ---------------------------------------------------------------------------
#define K1_WS 0
#define K1_ES 16896
#define K1_XS 25088
#define K1_BC 33404
#define K1_TK 33532
#define K1_SMEM_FLOATS 33596

__global__ void __launch_bounds__(256) k_tree_encode(const int* __restrict__ tokens,
                                                     const float* __restrict__ emb,
                                                     const float* __restrict__ bc)
{
    extern __shared__ float sm[];
    float* ws  = sm + K1_WS;
    float* es  = sm + K1_ES;
    float* xs  = sm + K1_XS;
    float* bcs = sm + K1_BC;
    int*   tks = (int*)(sm + K1_TK);

    const int bl  = blockIdx.x;   // b*L + l
    const int tid = threadIdx.x;

    if (tid < TT) tks[tid] = tokens[bl * TT + tid];
    if (tid < CC) bcs[tid] = bc[tid];

    // load transposed Wc: coalesced global, conflict-free shared stores
    for (int idx = tid; idx < (EE * CC) / 4; idx += 256) {
        int k  = idx >> 5;
        int c4 = (idx & 31) << 2;
        float4 v = ((const float4*)d_WcT)[idx];
        *(float4*)&ws[k * 132 + c4] = v;
    }
    __syncthreads();   // tks ready

    // gather 63 embedding rows (row 63 zero-padded)
    for (int idx = tid; idx < (64 * EE) / 4; idx += 256) {
        int t  = idx >> 5;
        int c4 = (idx & 31) << 2;
        float4 v = make_float4(0.f, 0.f, 0.f, 0.f);
        if (t < TT) v = *(const float4*)&emb[(long)tks[t] * EE + c4];
        *(float4*)&es[t * 128 + c4] = v;
    }
    __syncthreads();

    // projection: warp w handles nodes [8w, 8w+8); lanes cover all 128 channels
    const int w    = tid >> 5;
    const int lane = tid & 31;
    const int c4   = lane << 2;

    #pragma unroll
    for (int grp = 0; grp < 2; grp++) {
        const int tbase = w * 8 + grp * 4;
        float acc[4][4];
        #pragma unroll
        for (int n = 0; n < 4; n++) {
            acc[n][0] = 0.f; acc[n][1] = 0.f; acc[n][2] = 0.f; acc[n][3] = 0.f;
        }
        for (int k = 0; k < EE; k += 4) {
            float4 e4[4];
            #pragma unroll
            for (int n = 0; n < 4; n++) e4[n] = *(float4*)&es[(tbase + n) * 128 + k];
            #pragma unroll
            for (int kk = 0; kk < 4; kk++) {
                float4 wv = *(float4*)&ws[(k + kk) * 132 + c4];
                #pragma unroll
                for (int n = 0; n < 4; n++) {
                    float ev = (kk == 0) ? e4[n].x : (kk == 1) ? e4[n].y
                             : (kk == 2) ? e4[n].z : e4[n].w;
                    acc[n][0] += ev * wv.x;
                    acc[n][1] += ev * wv.y;
                    acc[n][2] += ev * wv.z;
                    acc[n][3] += ev * wv.w;
                }
            }
        }
        float4 bcv = *(float4*)&bcs[c4];
        #pragma unroll
        for (int n = 0; n < 4; n++) {
            int t = tbase + n;
            if (t < TT) {
                float4 r;
                r.x = acc[n][0] + bcv.x;
                r.y = acc[n][1] + bcv.y;
                r.z = acc[n][2] + bcv.z;
                r.w = acc[n][3] + bcv.w;
                *(float4*)&xs[t * 132 + c4] = r;
            }
        }
    }
    __syncthreads();

    // heap accumulation + max + relu (per-channel, fully independent)
    if (tid < CC) {
        const int c = tid;
        float m = -3.0e38f;
        #pragma unroll
        for (int t = TT - 1; t >= 31; t--) m = fmaxf(m, xs[t * 132 + c]);
        #pragma unroll
        for (int t = 30; t >= 0; t--) {
            float v = xs[t * 132 + c] + xs[(2 * t + 1) * 132 + c] + xs[(2 * t + 2) * 132 + c];
            xs[t * 132 + c] = v;
            m = fmaxf(m, v);
        }
        d_enc[bl * CC + c] = fmaxf(m, 0.f);
    }
}

// ---------------------------------------------------------------------------
// K2: gi[d] = enc @ Wih[d]^T + bih[d]   (time-parallel part of the GRU)
// Tiles: 64 rows (b,l) x 128 gate columns, K=128. grid (64, 6, 2)
// ---------------------------------------------------------------------------
#define K2_WS 0
#define K2_ES 16896
#define K2_BI 25088
#define K2_SMEM_FLOATS 25216

__global__ void __launch_bounds__(256) k_gi(const float* __restrict__ bih_f,
                                            const float* __restrict__ bih_b)
{
    extern __shared__ float sm[];
    float* ws  = sm + K2_WS;   // [128][132]  Wih^T tile [k][g]
    float* es  = sm + K2_ES;   // [64][128]   enc tile
    float* bis = sm + K2_BI;   // [128]

    const int mt = blockIdx.x;
    const int nt = blockIdx.y;
    const int d  = blockIdx.z;
    const int m0 = mt * 64;
    const int g0 = nt * 128;
    const int tid = threadIdx.x;

    const float* WT  = d ? d_WihT1 : d_WihT0;
    const float* bih = d ? bih_b   : bih_f;
    float*       gi  = d ? d_gi1   : d_gi0;

    for (int idx = tid; idx < (128 * 128) / 4; idx += 256) {
        int k  = idx >> 5;
        int j4 = (idx & 31) << 2;
        float4 v = *(const float4*)&WT[k * GG + g0 + j4];
        *(float4*)&ws[k * 132 + j4] = v;
    }
    for (int idx = tid; idx < (64 * 128) / 4; idx += 256) {
        int i  = idx >> 5;
        int k4 = (idx & 31) << 2;
        float4 v = *(const float4*)&d_enc[(m0 + i) * CC + k4];
        *(float4*)&es[i * 128 + k4] = v;
    }
    if (tid < 128) bis[tid] = bih[g0 + tid];
    __syncthreads();

    const int w    = tid >> 5;
    const int lane = tid & 31;
    const int c4   = lane << 2;

    #pragma unroll
    for (int grp = 0; grp < 2; grp++) {
        const int ibase = w * 8 + grp * 4;
        float acc[4][4];
        #pragma unroll
        for (int n = 0; n < 4; n++) {
            acc[n][0] = 0.f; acc[n][1] = 0.f; acc[n][2] = 0.f; acc[n][3] = 0.f;
        }
        for (int k = 0; k < CC; k += 4) {
            float4 e4[4];
            #pragma unroll
            for (int n = 0; n < 4; n++) e4[n] = *(float4*)&es[(ibase + n) * 128 + k];
            #pragma unroll
            for (int kk = 0; kk < 4; kk++) {
                float4 wv = *(float4*)&ws[(k + kk) * 132 + c4];
                #pragma unroll
                for (int n = 0; n < 4; n++) {
                    float ev = (kk == 0) ? e4[n].x : (kk == 1) ? e4[n].y
                             : (kk == 2) ? e4[n].z : e4[n].w;
                    acc[n][0] += ev * wv.x;
                    acc[n][1] += ev * wv.y;
                    acc[n][2] += ev * wv.z;
                    acc[n][3] += ev * wv.w;
                }
            }
        }
        float4 bv = *(float4*)&bis[c4];
        #pragma unroll
        for (int n = 0; n < 4; n++) {
            float4 r;
            r.x = acc[n][0] + bv.x;
            r.y = acc[n][1] + bv.y;
            r.z = acc[n][2] + bv.z;
            r.w = acc[n][3] + bv.w;
            *(float4*)&gi[(long)(m0 + ibase + n) * GG + g0 + c4] = r;
        }
    }
}

// ---------------------------------------------------------------------------
// K3: persistent bidirectional GRU.
// 128 CTAs (64 per direction, all co-resident), 128 threads each.
// CTA owns 4 hidden units; thread (u = tid/32, b = tid%32) computes all
// 3 gates for its (b, unit) -> thread-local GRU update, running max in reg.
// Inter-step sync: per-direction atomic counter + spin (release/acquire via
// __threadfence; h reads use .cg to bypass stale L1).
// ---------------------------------------------------------------------------
#define K3_WH 0                 // [12][256] Whh rows (r,z,n) x 4 units
#define K3_HS 3072              // [32][260] staged h_prev (padded rows)
#define K3_BH (3072 + 8320)     // [12]
#define K3_SMEM_FLOATS (3072 + 8320 + 16)

__global__ void __launch_bounds__(128) k_gru(const float* __restrict__ Whh_f,
                                             const float* __restrict__ bhh_f,
                                             const float* __restrict__ Whh_b,
                                             const float* __restrict__ bhh_b,
                                             float* __restrict__ out)
{
    extern __shared__ float sm[];
    float* whs = sm + K3_WH;
    float* hsh = sm + K3_HS;
    float* bhs = sm + K3_BH;

    const int d   = blockIdx.x >> 6;   // direction
    const int grp = blockIdx.x & 63;   // unit group
    const int u0  = grp << 2;
    const int tid = threadIdx.x;

    const float* Whh = d ? Whh_b : Whh_f;
    const float* bhh = d ? bhh_b : bhh_f;
    const float* gi  = d ? d_gi1 : d_gi0;

    for (int idx = tid; idx < 12 * 256; idx += 128) {
        int row  = idx >> 8;           // 0..11  (gate*4 + uu)
        int k    = idx & 255;
        int gate = row >> 2, uu = row & 3;
        whs[row * 256 + k] = Whh[(gate * HH + u0 + uu) * HH + k];
    }
    if (tid < 12) {
        int gate = tid >> 2, uu = tid & 3;
        bhs[tid] = bhh[gate * HH + u0 + uu];
    }

    const int u  = tid >> 5;
    const int b  = tid & 31;
    const int uc = u0 + u;

    float mx = -3.0e38f;
    __syncthreads();

    for (int s = 0; s < LL; s++) {
        const int  t     = d ? (LL - 1 - s) : s;
        const long gbase = ((long)b * LL + t) * GG + uc;
        // gi loads are independent of h -> issue before the stage
        const float gir = gi[gbase];
        const float giz = gi[gbase + HH];
        const float gin = gi[gbase + 2 * HH];

        const float* hprev = d_hbuf[d][s & 1];
        float*       hnext = d_hbuf[d][(s & 1) ^ 1];

        // stage h_prev (32x256) into shared; .cg to dodge stale L1
        for (int f = tid; f < 2048; f += 128) {
            int bb = f >> 6;
            int k4 = (f & 63) << 2;
            float4 v = __ldcg((const float4*)&hprev[bb * HH + k4]);
            *(float4*)&hsh[bb * 260 + k4] = v;
        }
        __syncthreads();

        float ar = bhs[u], az = bhs[4 + u], an = bhs[8 + u];
        const float* hrow = &hsh[b * 260];
        const float* wr   = &whs[u * 256];
        const float* wz   = &whs[(4 + u) * 256];
        const float* wn   = &whs[(8 + u) * 256];
        #pragma unroll 4
        for (int k = 0; k < HH; k += 4) {
            float4 h4  = *(const float4*)&hrow[k];
            float4 w4r = *(const float4*)&wr[k];
            float4 w4z = *(const float4*)&wz[k];
            float4 w4n = *(const float4*)&wn[k];
            ar += h4.x * w4r.x + h4.y * w4r.y + h4.z * w4r.z + h4.w * w4r.w;
            az += h4.x * w4z.x + h4.y * w4z.y + h4.z * w4z.z + h4.w * w4z.w;
            an += h4.x * w4n.x + h4.y * w4n.y + h4.z * w4n.z + h4.w * w4n.w;
        }
        const float hp = hrow[uc];
        const float r  = 1.f / (1.f + __expf(-(gir + ar)));
        const float z  = 1.f / (1.f + __expf(-(giz + az)));
        const float nn = tanhf(gin + r * an);
        const float hn = (1.f - z) * nn + z * hp;
        mx = fmaxf(mx, hn);
        hnext[b * HH + uc] = hn;

        // step barrier: release writes, arrive, spin, acquire
        __threadfence();
        __syncthreads();
        if (tid == 0) {
            atomicAdd(&d_bar[d], 1u);
            const unsigned target = 64u * (unsigned)(s + 1);
            while (*((volatile unsigned*)&d_bar[d]) < target) { }
        }
        __syncthreads();
    }

    // output (B, 512): fwd hidden -> cols [0,256), bwd -> [256,512)
    out[b * 512 + d * 256 + uc] = mx;
}

// ---------------------------------------------------------------------------
// kernel_launch
// ---------------------------------------------------------------------------
extern "C" void kernel_launch(void* const* d_in, const int* in_sizes, int n_in,
                              void* d_out, int out_size)
{
    const int*   tokens = (const int*)  d_in[0];
    const float* emb    = (const float*)d_in[1];
    const float* Wc     = (const float*)d_in[2];
    const float* bc     = (const float*)d_in[3];
    const float* Wih_f  = (const float*)d_in[4];
    const float* Whh_f  = (const float*)d_in[5];
    const float* bih_f  = (const float*)d_in[6];
    const float* bhh_f  = (const float*)d_in[7];
    const float* Wih_b  = (const float*)d_in[8];
    const float* Whh_b  = (const float*)d_in[9];
    const float* bih_b  = (const float*)d_in[10];
    const float* bhh_b  = (const float*)d_in[11];
    float* out = (float*)d_out;

    const int SM1 = K1_SMEM_FLOATS * 4;
    const int SM2 = K2_SMEM_FLOATS * 4;
    const int SM3 = K3_SMEM_FLOATS * 4;

    cudaFuncSetAttribute(k_tree_encode, cudaFuncAttributeMaxDynamicSharedMemorySize, SM1);
    cudaFuncSetAttribute(k_gi,          cudaFuncAttributeMaxDynamicSharedMemorySize, SM2);
    cudaFuncSetAttribute(k_gru,         cudaFuncAttributeMaxDynamicSharedMemorySize, SM3);

    k_setup<<<128, 256>>>(Wc, Wih_f, Wih_b);
    k_tree_encode<<<BB * LL, 256, SM1>>>(tokens, emb, bc);
    dim3 g2(64, 6, 2);
    k_gi<<<g2, 256, SM2>>>(bih_f, bih_b);
    k_gru<<<128, 128, SM3>>>(Whh_f, bhh_f, Whh_b, bhh_b, out);
}

// round 2
// speedup vs baseline: 1.3116x; 1.3116x over previous
#include <cuda_runtime.h>
#include <cuda_bf16.h>

// Problem constants (fixed by the dataset)
#define BB 32      // batch
#define LL 128     // sequence length
#define TT 63      // tree nodes (2^6 - 1)
#define EE 128     // embedding dim
#define CC 128     // conv/encoder channels
#define HH 256     // GRU hidden
#define GG 768     // 3*H gate columns

// ---------------------------------------------------------------------------
// Device scratch (static allocations only — no cudaMalloc allowed)
// ---------------------------------------------------------------------------
__device__ float d_WcT[EE * CC];          // [e][c]  (Wc transposed)
__device__ float d_WihT0[CC * GG];        // [k][g]  forward  Wih^T
__device__ float d_WihT1[CC * GG];        // [k][g]  backward Wih^T
__device__ float d_enc[BB * LL * CC];     // encoder output (b*L+l, c)
__device__ float d_gi0[(long)BB * LL * GG]; // precomputed input gates, fwd
__device__ float d_gi1[(long)BB * LL * GG]; // precomputed input gates, bwd
__device__ float d_hbuf[2][2][BB * HH];   // [dir][buf][b][k] double-buffered h
__device__ unsigned int d_bar[2];         // per-direction step barrier counters

// ---------------------------------------------------------------------------
// Setup: transpose weights, zero h buffers and barrier counters.
// ---------------------------------------------------------------------------
__global__ void k_setup(const float* __restrict__ Wc,
                        const float* __restrict__ Wih_f,
                        const float* __restrict__ Wih_b)
{
    const int i      = blockIdx.x * blockDim.x + threadIdx.x;
    const int stride = gridDim.x * blockDim.x;

    for (int idx = i; idx < EE * CC; idx += stride) {
        int e = idx / CC, c = idx % CC;
        d_WcT[e * CC + c] = Wc[c * EE + e];
    }
    for (int idx = i; idx < CC * GG; idx += stride) {
        int k = idx / GG, g = idx % GG;
        d_WihT0[idx] = Wih_f[g * CC + k];
        d_WihT1[idx] = Wih_b[g * CC + k];
    }
    for (int idx = i; idx < 2 * 2 * BB * HH; idx += stride) {
        ((float*)d_hbuf)[idx] = 0.f;
    }
    if (i < 2) d_bar[i] = 0u;
}

// ---------------------------------------------------------------------------
// K1: fused tree encoder. One CTA per (b,l).  (unchanged from R1)
// ---------------------------------------------------------------------------
#define K1_WS 0
#define K1_ES 16896
#define K1_XS 25088
#define K1_BC 33404
#define K1_TK 33532
#define K1_SMEM_FLOATS 33596

__global__ void __launch_bounds__(256) k_tree_encode(const int* __restrict__ tokens,
                                                     const float* __restrict__ emb,
                                                     const float* __restrict__ bc)
{
    extern __shared__ float sm[];
    float* ws  = sm + K1_WS;
    float* es  = sm + K1_ES;
    float* xs  = sm + K1_XS;
    float* bcs = sm + K1_BC;
    int*   tks = (int*)(sm + K1_TK);

    const int bl  = blockIdx.x;
    const int tid = threadIdx.x;

    if (tid < TT) tks[tid] = tokens[bl * TT + tid];
    if (tid < CC) bcs[tid] = bc[tid];

    for (int idx = tid; idx < (EE * CC) / 4; idx += 256) {
        int k  = idx >> 5;
        int c4 = (idx & 31) << 2;
        float4 v = ((const float4*)d_WcT)[idx];
        *(float4*)&ws[k * 132 + c4] = v;
    }
    __syncthreads();

    for (int idx = tid; idx < (64 * EE) / 4; idx += 256) {
        int t  = idx >> 5;
        int c4 = (idx & 31) << 2;
        float4 v = make_float4(0.f, 0.f, 0.f, 0.f);
        if (t < TT) v = *(const float4*)&emb[(long)tks[t] * EE + c4];
        *(float4*)&es[t * 128 + c4] = v;
    }
    __syncthreads();

    const int w    = tid >> 5;
    const int lane = tid & 31;
    const int c4   = lane << 2;

    #pragma unroll
    for (int grp = 0; grp < 2; grp++) {
        const int tbase = w * 8 + grp * 4;
        float acc[4][4];
        #pragma unroll
        for (int n = 0; n < 4; n++) {
            acc[n][0] = 0.f; acc[n][1] = 0.f; acc[n][2] = 0.f; acc[n][3] = 0.f;
        }
        for (int k = 0; k < EE; k += 4) {
            float4 e4[4];
            #pragma unroll
            for (int n = 0; n < 4; n++) e4[n] = *(float4*)&es[(tbase + n) * 128 + k];
            #pragma unroll
            for (int kk = 0; kk < 4; kk++) {
                float4 wv = *(float4*)&ws[(k + kk) * 132 + c4];
                #pragma unroll
                for (int n = 0; n < 4; n++) {
                    float ev = (kk == 0) ? e4[n].x : (kk == 1) ? e4[n].y
                             : (kk == 2) ? e4[n].z : e4[n].w;
                    acc[n][0] += ev * wv.x;
                    acc[n][1] += ev * wv.y;
                    acc[n][2] += ev * wv.z;
                    acc[n][3] += ev * wv.w;
                }
            }
        }
        float4 bcv = *(float4*)&bcs[c4];
        #pragma unroll
        for (int n = 0; n < 4; n++) {
            int t = tbase + n;
            if (t < TT) {
                float4 r;
                r.x = acc[n][0] + bcv.x;
                r.y = acc[n][1] + bcv.y;
                r.z = acc[n][2] + bcv.z;
                r.w = acc[n][3] + bcv.w;
                *(float4*)&xs[t * 132 + c4] = r;
            }
        }
    }
    __syncthreads();

    if (tid < CC) {
        const int c = tid;
        float m = -3.0e38f;
        #pragma unroll
        for (int t = TT - 1; t >= 31; t--) m = fmaxf(m, xs[t * 132 + c]);
        #pragma unroll
        for (int t = 30; t >= 0; t--) {
            float v = xs[t * 132 + c] + xs[(2 * t + 1) * 132 + c] + xs[(2 * t + 2) * 132 + c];
            xs[t * 132 + c] = v;
            m = fmaxf(m, v);
        }
        d_enc[bl * CC + c] = fmaxf(m, 0.f);
    }
}

// ---------------------------------------------------------------------------
// K2: gi[d] = enc @ Wih[d]^T + bih[d]     (unchanged from R1)
// ---------------------------------------------------------------------------
#define K2_WS 0
#define K2_ES 16896
#define K2_BI 25088
#define K2_SMEM_FLOATS 25216

__global__ void __launch_bounds__(256) k_gi(const float* __restrict__ bih_f,
                                            const float* __restrict__ bih_b)
{
    extern __shared__ float sm[];
    float* ws  = sm + K2_WS;
    float* es  = sm + K2_ES;
    float* bis = sm + K2_BI;

    const int mt = blockIdx.x;
    const int nt = blockIdx.y;
    const int d  = blockIdx.z;
    const int m0 = mt * 64;
    const int g0 = nt * 128;
    const int tid = threadIdx.x;

    const float* WT  = d ? d_WihT1 : d_WihT0;
    const float* bih = d ? bih_b   : bih_f;
    float*       gi  = d ? d_gi1   : d_gi0;

    for (int idx = tid; idx < (128 * 128) / 4; idx += 256) {
        int k  = idx >> 5;
        int j4 = (idx & 31) << 2;
        float4 v = *(const float4*)&WT[k * GG + g0 + j4];
        *(float4*)&ws[k * 132 + j4] = v;
    }
    for (int idx = tid; idx < (64 * 128) / 4; idx += 256) {
        int i  = idx >> 5;
        int k4 = (idx & 31) << 2;
        float4 v = *(const float4*)&d_enc[(m0 + i) * CC + k4];
        *(float4*)&es[i * 128 + k4] = v;
    }
    if (tid < 128) bis[tid] = bih[g0 + tid];
    __syncthreads();

    const int w    = tid >> 5;
    const int lane = tid & 31;
    const int c4   = lane << 2;

    #pragma unroll
    for (int grp = 0; grp < 2; grp++) {
        const int ibase = w * 8 + grp * 4;
        float acc[4][4];
        #pragma unroll
        for (int n = 0; n < 4; n++) {
            acc[n][0] = 0.f; acc[n][1] = 0.f; acc[n][2] = 0.f; acc[n][3] = 0.f;
        }
        for (int k = 0; k < CC; k += 4) {
            float4 e4[4];
            #pragma unroll
            for (int n = 0; n < 4; n++) e4[n] = *(float4*)&es[(ibase + n) * 128 + k];
            #pragma unroll
            for (int kk = 0; kk < 4; kk++) {
                float4 wv = *(float4*)&ws[(k + kk) * 132 + c4];
                #pragma unroll
                for (int n = 0; n < 4; n++) {
                    float ev = (kk == 0) ? e4[n].x : (kk == 1) ? e4[n].y
                             : (kk == 2) ? e4[n].z : e4[n].w;
                    acc[n][0] += ev * wv.x;
                    acc[n][1] += ev * wv.y;
                    acc[n][2] += ev * wv.z;
                    acc[n][3] += ev * wv.w;
                }
            }
        }
        float4 bv = *(float4*)&bis[c4];
        #pragma unroll
        for (int n = 0; n < 4; n++) {
            float4 r;
            r.x = acc[n][0] + bv.x;
            r.y = acc[n][1] + bv.y;
            r.z = acc[n][2] + bv.z;
            r.w = acc[n][3] + bv.w;
            *(float4*)&gi[(long)(m0 + ibase + n) * GG + g0 + c4] = r;
        }
    }
}

// ---------------------------------------------------------------------------
// K3 v2: persistent bidirectional GRU, split-K, 512 threads/CTA.
// 128 CTAs (64 per direction, all co-resident). CTA owns 4 hidden units.
// Warp w -> (u = w>>2, s = w&3): computes k-slice [s*64, s*64+64) of the
// 3 gate dot-products for unit u, all 32 batches (lane = b).
// h tile is XOR-swizzled in shared for conflict-free LDS.128.
// Partials reduced via shared; s==0 warps apply the GRU nonlinearity.
// Shared layout (floats):
//   whs [12][256]          @ 0      (Whh rows: gate*4+uu)
//   hs4 float4[32][64]     @ 3072   (swizzled h_prev tile)
//   red [16][3][32]        @ 11264  (split-K partials)
// ---------------------------------------------------------------------------
#define K3_SMEM_FLOATS (3072 + 8192 + 1536)

__global__ void __launch_bounds__(512) k_gru(const float* __restrict__ Whh_f,
                                             const float* __restrict__ bhh_f,
                                             const float* __restrict__ Whh_b,
                                             const float* __restrict__ bhh_b,
                                             float* __restrict__ out)
{
    extern __shared__ float sm[];
    float*  whs = sm;                       // 12 * 256
    float4* hs4 = (float4*)(sm + 3072);     // 32 * 64 float4 (swizzled)
    float*  red = sm + 3072 + 8192;         // 16 * 3 * 32

    const int d    = blockIdx.x >> 6;
    const int grp  = blockIdx.x & 63;
    const int u0   = grp << 2;
    const int tid  = threadIdx.x;
    const int w    = tid >> 5;
    const int lane = tid & 31;
    const int u    = w >> 2;      // 0..3 unit within CTA
    const int s    = w & 3;       // 0..3 k-split
    const int b    = lane;
    const int bx   = b & 7;       // swizzle key
    const int uc   = u0 + u;

    const float* Whh = d ? Whh_b : Whh_f;
    const float* bhh = d ? bhh_b : bhh_f;
    const float* gi  = d ? d_gi1 : d_gi0;

    // load Whh rows (gate*4 + uu) into shared, float4 coalesced
    for (int idx = tid; idx < (12 * 256) / 4; idx += 512) {
        int row  = idx >> 6;               // 0..11
        int k4   = (idx & 63) << 2;
        int gate = row >> 2, uu = row & 3;
        float4 v = *(const float4*)&Whh[(gate * HH + u0 + uu) * HH + k4];
        *(float4*)&whs[row * 256 + k4] = v;
    }

    // biases for the finalizing warps
    float br = 0.f, bz = 0.f, bn = 0.f;
    if (s == 0) {
        br = bhh[uc];
        bz = bhh[HH + uc];
        bn = bhh[2 * HH + uc];
    }

    float mx = -3.0e38f;
    __syncthreads();

    for (int st = 0; st < LL; st++) {
        const int t = d ? (LL - 1 - st) : st;

        // prefetch gi early (independent of h)
        float gir = 0.f, giz = 0.f, gin = 0.f;
        if (s == 0) {
            const long gb = ((long)b * LL + t) * GG + uc;
            gir = __ldg(&gi[gb]);
            giz = __ldg(&gi[gb + HH]);
            gin = __ldg(&gi[gb + 2 * HH]);
        }

        const float* hprev = d_hbuf[d][st & 1];
        float*       hnext = d_hbuf[d][(st & 1) ^ 1];

        // stage h_prev 32x256 -> swizzled shared tile (.cg: bypass stale L1)
        #pragma unroll
        for (int j = 0; j < 4; j++) {
            int idx = tid + j * 512;
            int bb  = idx >> 6;
            int kk  = idx & 63;
            float4 v = __ldcg((const float4*)hprev + idx);
            hs4[bb * 64 + (kk ^ (bb & 7))] = v;
        }
        __syncthreads();

        // split-K partial dot-products (64 k-values per warp)
        float ar = 0.f, az = 0.f, an = 0.f;
        {
            const float*  wr = &whs[u * 256 + s * 64];
            const float*  wz = &whs[(4 + u) * 256 + s * 64];
            const float*  wn = &whs[(8 + u) * 256 + s * 64];
            const float4* hb = &hs4[b * 64];
            const int     k0 = s * 16;
            #pragma unroll
            for (int i = 0; i < 16; i++) {
                float4 h4  = hb[(k0 + i) ^ bx];
                float4 w4r = *(const float4*)&wr[i * 4];
                float4 w4z = *(const float4*)&wz[i * 4];
                float4 w4n = *(const float4*)&wn[i * 4];
                ar += h4.x * w4r.x + h4.y * w4r.y + h4.z * w4r.z + h4.w * w4r.w;
                az += h4.x * w4z.x + h4.y * w4z.y + h4.z * w4z.z + h4.w * w4z.w;
                an += h4.x * w4n.x + h4.y * w4n.y + h4.z * w4n.z + h4.w * w4n.w;
            }
        }

        // publish partials
        red[(w * 3 + 0) * 32 + b] = ar;
        red[(w * 3 + 1) * 32 + b] = az;
        red[(w * 3 + 2) * 32 + b] = an;
        __syncthreads();

        // finalize (s==0 warps): sum splits, GRU nonlinearity, store h
        if (s == 0) {
            float sr = 0.f, sz = 0.f, sn = 0.f;
            #pragma unroll
            for (int ss = 0; ss < 4; ss++) {
                const int rw = u * 4 + ss;
                sr += red[(rw * 3 + 0) * 32 + b];
                sz += red[(rw * 3 + 1) * 32 + b];
                sn += red[(rw * 3 + 2) * 32 + b];
            }
            // h_prev[b][uc] from the swizzled tile
            float4 hv = hs4[b * 64 + ((uc >> 2) ^ bx)];
            const int cmp = uc & 3;
            const float hp = (cmp == 0) ? hv.x : (cmp == 1) ? hv.y
                           : (cmp == 2) ? hv.z : hv.w;

            const float r  = 1.f / (1.f + __expf(-(gir + sr + br)));
            const float z  = 1.f / (1.f + __expf(-(giz + sz + bz)));
            const float nn = tanhf(gin + r * (sn + bn));
            const float hn = (1.f - z) * nn + z * hp;
            mx = fmaxf(mx, hn);
            hnext[b * HH + uc] = hn;
        }

        // inter-CTA step barrier (per direction)
        __threadfence();
        __syncthreads();
        if (tid == 0) {
            atomicAdd(&d_bar[d], 1u);
            const unsigned target = 64u * (unsigned)(st + 1);
            while (*((volatile unsigned*)&d_bar[d]) < target) { }
            __threadfence();
        }
        __syncthreads();
    }

    if (s == 0) out[b * 512 + d * 256 + uc] = mx;
}

// ---------------------------------------------------------------------------
// kernel_launch
// ---------------------------------------------------------------------------
extern "C" void kernel_launch(void* const* d_in, const int* in_sizes, int n_in,
                              void* d_out, int out_size)
{
    const int*   tokens = (const int*)  d_in[0];
    const float* emb    = (const float*)d_in[1];
    const float* Wc     = (const float*)d_in[2];
    const float* bc     = (const float*)d_in[3];
    const float* Wih_f  = (const float*)d_in[4];
    const float* Whh_f  = (const float*)d_in[5];
    const float* bih_f  = (const float*)d_in[6];
    const float* bhh_f  = (const float*)d_in[7];
    const float* Wih_b  = (const float*)d_in[8];
    const float* Whh_b  = (const float*)d_in[9];
    const float* bih_b  = (const float*)d_in[10];
    const float* bhh_b  = (const float*)d_in[11];
    float* out = (float*)d_out;

    const int SM1 = K1_SMEM_FLOATS * 4;
    const int SM2 = K2_SMEM_FLOATS * 4;
    const int SM3 = K3_SMEM_FLOATS * 4;

    cudaFuncSetAttribute(k_tree_encode, cudaFuncAttributeMaxDynamicSharedMemorySize, SM1);
    cudaFuncSetAttribute(k_gi,          cudaFuncAttributeMaxDynamicSharedMemorySize, SM2);
    cudaFuncSetAttribute(k_gru,         cudaFuncAttributeMaxDynamicSharedMemorySize, SM3);

    k_setup<<<128, 256>>>(Wc, Wih_f, Wih_b);
    k_tree_encode<<<BB * LL, 256, SM1>>>(tokens, emb, bc);
    dim3 g2(64, 6, 2);
    k_gi<<<g2, 256, SM2>>>(bih_f, bih_b);
    k_gru<<<128, 512, SM3>>>(Whh_f, bhh_f, Whh_b, bhh_b, out);
}

// round 3
// speedup vs baseline: 1.9807x; 1.5101x over previous
#include <cuda_runtime.h>
#include <cuda_bf16.h>
#include <cstdint>

// Problem constants (fixed by the dataset)
#define BB 32      // batch
#define LL 128     // sequence length
#define TT 63      // tree nodes (2^6 - 1)
#define EE 128     // embedding dim
#define CC 128     // conv/encoder channels
#define HH 256     // GRU hidden
#define GG 768     // 3*H gate columns

// ---------------------------------------------------------------------------
// Device scratch (static allocations only — no cudaMalloc allowed)
// ---------------------------------------------------------------------------
__device__ float d_WcT[EE * CC];            // [e][c]  (Wc transposed)
__device__ float d_WihT0[CC * GG];          // [k][g]  forward  Wih^T
__device__ float d_WihT1[CC * GG];          // [k][g]  backward Wih^T
__device__ float d_enc[BB * LL * CC];       // encoder output (b*L+l, c)
__device__ float d_gi0[(long)BB * LL * GG]; // precomputed input gates, fwd
__device__ float d_gi1[(long)BB * LL * GG]; // precomputed input gates, bwd

// ---------------------------------------------------------------------------
// Setup: transpose weights.
// ---------------------------------------------------------------------------
__global__ void k_setup(const float* __restrict__ Wc,
                        const float* __restrict__ Wih_f,
                        const float* __restrict__ Wih_b)
{
    const int i      = blockIdx.x * blockDim.x + threadIdx.x;
    const int stride = gridDim.x * blockDim.x;

    for (int idx = i; idx < EE * CC; idx += stride) {
        int e = idx / CC, c = idx % CC;
        d_WcT[e * CC + c] = Wc[c * EE + e];
    }
    for (int idx = i; idx < CC * GG; idx += stride) {
        int k = idx / GG, g = idx % GG;
        d_WihT0[idx] = Wih_f[g * CC + k];
        d_WihT1[idx] = Wih_b[g * CC + k];
    }
}

// ---------------------------------------------------------------------------
// K1: fused tree encoder. One CTA per (b,l).  (unchanged)
// ---------------------------------------------------------------------------
#define K1_WS 0
#define K1_ES 16896
#define K1_XS 25088
#define K1_BC 33404
#define K1_TK 33532
#define K1_SMEM_FLOATS 33596

__global__ void __launch_bounds__(256) k_tree_encode(const int* __restrict__ tokens,
                                                     const float* __restrict__ emb,
                                                     const float* __restrict__ bc)
{
    extern __shared__ float sm[];
    float* ws  = sm + K1_WS;
    float* es  = sm + K1_ES;
    float* xs  = sm + K1_XS;
    float* bcs = sm + K1_BC;
    int*   tks = (int*)(sm + K1_TK);

    const int bl  = blockIdx.x;
    const int tid = threadIdx.x;

    if (tid < TT) tks[tid] = tokens[bl * TT + tid];
    if (tid < CC) bcs[tid] = bc[tid];

    for (int idx = tid; idx < (EE * CC) / 4; idx += 256) {
        int k  = idx >> 5;
        int c4 = (idx & 31) << 2;
        float4 v = ((const float4*)d_WcT)[idx];
        *(float4*)&ws[k * 132 + c4] = v;
    }
    __syncthreads();

    for (int idx = tid; idx < (64 * EE) / 4; idx += 256) {
        int t  = idx >> 5;
        int c4 = (idx & 31) << 2;
        float4 v = make_float4(0.f, 0.f, 0.f, 0.f);
        if (t < TT) v = *(const float4*)&emb[(long)tks[t] * EE + c4];
        *(float4*)&es[t * 128 + c4] = v;
    }
    __syncthreads();

    const int w    = tid >> 5;
    const int lane = tid & 31;
    const int c4   = lane << 2;

    #pragma unroll
    for (int grp = 0; grp < 2; grp++) {
        const int tbase = w * 8 + grp * 4;
        float acc[4][4];
        #pragma unroll
        for (int n = 0; n < 4; n++) {
            acc[n][0] = 0.f; acc[n][1] = 0.f; acc[n][2] = 0.f; acc[n][3] = 0.f;
        }
        for (int k = 0; k < EE; k += 4) {
            float4 e4[4];
            #pragma unroll
            for (int n = 0; n < 4; n++) e4[n] = *(float4*)&es[(tbase + n) * 128 + k];
            #pragma unroll
            for (int kk = 0; kk < 4; kk++) {
                float4 wv = *(float4*)&ws[(k + kk) * 132 + c4];
                #pragma unroll
                for (int n = 0; n < 4; n++) {
                    float ev = (kk == 0) ? e4[n].x : (kk == 1) ? e4[n].y
                             : (kk == 2) ? e4[n].z : e4[n].w;
                    acc[n][0] += ev * wv.x;
                    acc[n][1] += ev * wv.y;
                    acc[n][2] += ev * wv.z;
                    acc[n][3] += ev * wv.w;
                }
            }
        }
        float4 bcv = *(float4*)&bcs[c4];
        #pragma unroll
        for (int n = 0; n < 4; n++) {
            int t = tbase + n;
            if (t < TT) {
                float4 r;
                r.x = acc[n][0] + bcv.x;
                r.y = acc[n][1] + bcv.y;
                r.z = acc[n][2] + bcv.z;
                r.w = acc[n][3] + bcv.w;
                *(float4*)&xs[t * 132 + c4] = r;
            }
        }
    }
    __syncthreads();

    if (tid < CC) {
        const int c = tid;
        float m = -3.0e38f;
        #pragma unroll
        for (int t = TT - 1; t >= 31; t--) m = fmaxf(m, xs[t * 132 + c]);
        #pragma unroll
        for (int t = 30; t >= 0; t--) {
            float v = xs[t * 132 + c] + xs[(2 * t + 1) * 132 + c] + xs[(2 * t + 2) * 132 + c];
            xs[t * 132 + c] = v;
            m = fmaxf(m, v);
        }
        d_enc[bl * CC + c] = fmaxf(m, 0.f);
    }
}

// ---------------------------------------------------------------------------
// K2: gi[d] = enc @ Wih[d]^T + bih[d]     (unchanged)
// ---------------------------------------------------------------------------
#define K2_WS 0
#define K2_ES 16896
#define K2_BI 25088
#define K2_SMEM_FLOATS 25216

__global__ void __launch_bounds__(256) k_gi(const float* __restrict__ bih_f,
                                            const float* __restrict__ bih_b)
{
    extern __shared__ float sm[];
    float* ws  = sm + K2_WS;
    float* es  = sm + K2_ES;
    float* bis = sm + K2_BI;

    const int mt = blockIdx.x;
    const int nt = blockIdx.y;
    const int d  = blockIdx.z;
    const int m0 = mt * 64;
    const int g0 = nt * 128;
    const int tid = threadIdx.x;

    const float* WT  = d ? d_WihT1 : d_WihT0;
    const float* bih = d ? bih_b   : bih_f;
    float*       gi  = d ? d_gi1   : d_gi0;

    for (int idx = tid; idx < (128 * 128) / 4; idx += 256) {
        int k  = idx >> 5;
        int j4 = (idx & 31) << 2;
        float4 v = *(const float4*)&WT[k * GG + g0 + j4];
        *(float4*)&ws[k * 132 + j4] = v;
    }
    for (int idx = tid; idx < (64 * 128) / 4; idx += 256) {
        int i  = idx >> 5;
        int k4 = (idx & 31) << 2;
        float4 v = *(const float4*)&d_enc[(m0 + i) * CC + k4];
        *(float4*)&es[i * 128 + k4] = v;
    }
    if (tid < 128) bis[tid] = bih[g0 + tid];
    __syncthreads();

    const int w    = tid >> 5;
    const int lane = tid & 31;
    const int c4   = lane << 2;

    #pragma unroll
    for (int grp = 0; grp < 2; grp++) {
        const int ibase = w * 8 + grp * 4;
        float acc[4][4];
        #pragma unroll
        for (int n = 0; n < 4; n++) {
            acc[n][0] = 0.f; acc[n][1] = 0.f; acc[n][2] = 0.f; acc[n][3] = 0.f;
        }
        for (int k = 0; k < CC; k += 4) {
            float4 e4[4];
            #pragma unroll
            for (int n = 0; n < 4; n++) e4[n] = *(float4*)&es[(ibase + n) * 128 + k];
            #pragma unroll
            for (int kk = 0; kk < 4; kk++) {
                float4 wv = *(float4*)&ws[(k + kk) * 132 + c4];
                #pragma unroll
                for (int n = 0; n < 4; n++) {
                    float ev = (kk == 0) ? e4[n].x : (kk == 1) ? e4[n].y
                             : (kk == 2) ? e4[n].z : e4[n].w;
                    acc[n][0] += ev * wv.x;
                    acc[n][1] += ev * wv.y;
                    acc[n][2] += ev * wv.z;
                    acc[n][3] += ev * wv.w;
                }
            }
        }
        float4 bv = *(float4*)&bis[c4];
        #pragma unroll
        for (int n = 0; n < 4; n++) {
            float4 r;
            r.x = acc[n][0] + bv.x;
            r.y = acc[n][1] + bv.y;
            r.z = acc[n][2] + bv.z;
            r.w = acc[n][3] + bv.w;
            *(float4*)&gi[(long)(m0 + ibase + n) * GG + g0 + c4] = r;
        }
    }
}

// ---------------------------------------------------------------------------
// K3 v3: cluster-local bidirectional GRU. 32 clusters x 4 CTAs, 384 thr/CTA.
// Cluster cid: dir = cid>>4, batch pair = (cid&15)*2 + {0,1}.
// CTA rank cr owns units [cr*64, cr*64+64): 192 Whh rows held in REGISTERS
// (thread (row,half) keeps 128 weights). Full h for both batches lives in
// each CTA's smem (double-buffered); new h values are pushed to all peers
// via DSMEM st.shared::cluster, step boundary = cluster.sync. No atomics,
// no global-memory h traffic, no cross-cluster coupling.
// ---------------------------------------------------------------------------
__device__ __forceinline__ uint32_t smem_u32(const void* p) {
    uint32_t a;
    asm("{ .reg .u64 t; cvta.to.shared.u64 t, %1; cvt.u32.u64 %0, t; }"
        : "=r"(a) : "l"(p));
    return a;
}

__device__ __forceinline__ void st_cluster_f32(uint32_t local_addr, uint32_t rank, float v) {
    asm volatile(
        "{\n\t"
        ".reg .b32 r;\n\t"
        "mapa.shared::cluster.u32 r, %0, %1;\n\t"
        "st.shared::cluster.f32 [r], %2;\n\t"
        "}"
        :: "r"(local_addr), "r"(rank), "f"(v) : "memory");
}

__global__ void __launch_bounds__(384, 1) __cluster_dims__(4, 1, 1)
k_gru(const float* __restrict__ Whh_f, const float* __restrict__ bhh_f,
      const float* __restrict__ Whh_b, const float* __restrict__ bhh_b,
      float* __restrict__ out)
{
    __shared__ float hbuf[2][2][HH];   // [buf][bt][unit] — full h, both batches
    __shared__ float part[2][192];     // half-1 partial dots [bt][row]
    __shared__ float gates[2][192];    // completed gate pre-activations [bt][row]

    const int tid = threadIdx.x;
    uint32_t cr;
    asm("mov.u32 %0, %%cluster_ctarank;" : "=r"(cr));

    const int cid = blockIdx.x >> 2;       // cluster id 0..31
    const int d   = cid >> 4;              // direction
    const int bp  = cid & 15;              // batch pair -> batches 2bp, 2bp+1
    const int U0  = (int)cr << 6;          // this CTA's unit range base

    const float* Whh = d ? Whh_b : Whh_f;
    const float* bhh = d ? bhh_b : bhh_f;
    const float* gi  = d ? d_gi1 : d_gi0;

    // thread -> (row, half): warps 0-5 half 0, warps 6-11 half 1; lane = row%32
    const int w    = tid >> 5;
    const int lane = tid & 31;
    const int rw   = (w % 6) * 32 + lane;  // 0..191  (gate*64 + u)
    const int half = w / 6;                // 0 or 1

    // load this thread's 128 Whh weights into registers (once)
    const int gate = rw >> 6, uu = rw & 63;
    float4 wreg[32];
    {
        const float* wrow = &Whh[(gate * HH + U0 + uu) * HH + half * 128];
        #pragma unroll
        for (int i = 0; i < 32; i++) wreg[i] = *(const float4*)&wrow[i * 4];
    }

    // finalize-thread constants (tid < 128: u = tid&63, bt = tid>>6)
    const int u_f   = tid & 63;
    const int bt_f  = tid >> 6;
    const int bglob = bp * 2 + bt_f;
    float br = 0.f, bz = 0.f, bn = 0.f;
    uint32_t haddr0 = 0, haddr1 = 0;   // smem byte addr of hbuf[buf][bt_f][U0+u_f]
    if (tid < 128) {
        br = bhh[U0 + u_f];
        bz = bhh[HH + U0 + u_f];
        bn = bhh[2 * HH + U0 + u_f];
        haddr0 = smem_u32(&hbuf[0][bt_f][U0 + u_f]);
        haddr1 = smem_u32(&hbuf[1][bt_f][U0 + u_f]);
    }

    // init h0 = 0 (each CTA holds its own full copy)
    for (int i = tid; i < 2 * HH; i += 384) hbuf[0][i >> 8][i & 255] = 0.f;

    float mx = -3.0e38f;

    // all peers ready before any DSMEM traffic
    asm volatile("barrier.cluster.arrive.aligned;" ::: "memory");
    asm volatile("barrier.cluster.wait.aligned;"   ::: "memory");

    for (int st = 0; st < LL; st++) {
        const int p = st & 1;
        const int t = d ? (LL - 1 - st) : st;

        // prefetch gi (independent of h; hidden behind the dot products)
        float gir = 0.f, giz = 0.f, gin = 0.f;
        if (tid < 128) {
            const long gb = ((long)bglob * LL + t) * GG + U0 + u_f;
            gir = __ldg(&gi[gb]);
            giz = __ldg(&gi[gb + HH]);
            gin = __ldg(&gi[gb + 2 * HH]);
        }

        // dot products: all lanes of a warp share (half, batch) h address -> broadcast LDS
        float4 a0 = make_float4(0.f, 0.f, 0.f, 0.f);
        float4 a1 = make_float4(0.f, 0.f, 0.f, 0.f);
        {
            const float* h0 = &hbuf[p][0][half * 128];
            const float* h1 = &hbuf[p][1][half * 128];
            #pragma unroll
            for (int i = 0; i < 32; i++) {
                float4 wv = wreg[i];
                float4 x0 = *(const float4*)&h0[i * 4];
                float4 x1 = *(const float4*)&h1[i * 4];
                a0.x += wv.x * x0.x; a0.y += wv.y * x0.y;
                a0.z += wv.z * x0.z; a0.w += wv.w * x0.w;
                a1.x += wv.x * x1.x; a1.y += wv.y * x1.y;
                a1.z += wv.z * x1.z; a1.w += wv.w * x1.w;
            }
        }
        const float s0 = (a0.x + a0.y) + (a0.z + a0.w);
        const float s1 = (a1.x + a1.y) + (a1.z + a1.w);

        if (half == 1) {
            part[0][rw] = s0;
            part[1][rw] = s1;
        }
        __syncthreads();
        if (half == 0) {
            gates[0][rw] = s0 + part[0][rw];
            gates[1][rw] = s1 + part[1][rw];
        }
        __syncthreads();

        // finalize: 128 threads apply GRU nonlinearity, push h to all 4 CTAs
        if (tid < 128) {
            const float gr = gates[bt_f][u_f];
            const float gz = gates[bt_f][64 + u_f];
            const float gn = gates[bt_f][128 + u_f];
            const float hp = hbuf[p][bt_f][U0 + u_f];

            const float r  = 1.f / (1.f + __expf(-(gir + gr + br)));
            const float z  = 1.f / (1.f + __expf(-(giz + gz + bz)));
            const float nn = tanhf(gin + r * (gn + bn));
            const float hn = (1.f - z) * nn + z * hp;
            mx = fmaxf(mx, hn);

            hbuf[p ^ 1][bt_f][U0 + u_f] = hn;            // local copy
            const uint32_t ha = (p ^ 1) ? haddr1 : haddr0;
            #pragma unroll
            for (uint32_t rk = 0; rk < 4; rk++) {
                if (rk != cr) st_cluster_f32(ha, rk, hn); // peer copies
            }
        }

        // step boundary: DSMEM writes visible cluster-wide after this
        asm volatile("barrier.cluster.arrive.aligned;" ::: "memory");
        asm volatile("barrier.cluster.wait.aligned;"   ::: "memory");
    }

    if (tid < 128) out[bglob * 512 + d * 256 + U0 + u_f] = mx;
}

// ---------------------------------------------------------------------------
// kernel_launch
// ---------------------------------------------------------------------------
extern "C" void kernel_launch(void* const* d_in, const int* in_sizes, int n_in,
                              void* d_out, int out_size)
{
    const int*   tokens = (const int*)  d_in[0];
    const float* emb    = (const float*)d_in[1];
    const float* Wc     = (const float*)d_in[2];
    const float* bc     = (const float*)d_in[3];
    const float* Wih_f  = (const float*)d_in[4];
    const float* Whh_f  = (const float*)d_in[5];
    const float* bih_f  = (const float*)d_in[6];
    const float* bhh_f  = (const float*)d_in[7];
    const float* Wih_b  = (const float*)d_in[8];
    const float* Whh_b  = (const float*)d_in[9];
    const float* bih_b  = (const float*)d_in[10];
    const float* bhh_b  = (const float*)d_in[11];
    float* out = (float*)d_out;

    const int SM1 = K1_SMEM_FLOATS * 4;
    const int SM2 = K2_SMEM_FLOATS * 4;

    cudaFuncSetAttribute(k_tree_encode, cudaFuncAttributeMaxDynamicSharedMemorySize, SM1);
    cudaFuncSetAttribute(k_gi,          cudaFuncAttributeMaxDynamicSharedMemorySize, SM2);

    k_setup<<<128, 256>>>(Wc, Wih_f, Wih_b);
    k_tree_encode<<<BB * LL, 256, SM1>>>(tokens, emb, bc);
    dim3 g2(64, 6, 2);
    k_gi<<<g2, 256, SM2>>>(bih_f, bih_b);
    k_gru<<<128, 384>>>(Whh_f, bhh_f, Whh_b, bhh_b, out);
}

// round 4
// speedup vs baseline: 1.9976x; 1.0085x over previous
#include <cuda_runtime.h>
#include <cuda_bf16.h>
#include <cstdint>

// Problem constants (fixed by the dataset)
#define BB 32      // batch
#define LL 128     // sequence length
#define TT 63      // tree nodes (2^6 - 1)
#define EE 128     // embedding dim
#define CC 128     // conv/encoder channels
#define HH 256     // GRU hidden
#define GG 768     // 3*H gate columns

// ---------------------------------------------------------------------------
// Packed fp32x2 helpers (Blackwell f32x2 pipe; bitwise-identical fp32 rounding)
// ---------------------------------------------------------------------------
__device__ __forceinline__ unsigned long long fma2(unsigned long long a,
                                                   unsigned long long b,
                                                   unsigned long long c) {
    unsigned long long d;
    asm("fma.rn.f32x2 %0, %1, %2, %3;" : "=l"(d) : "l"(a), "l"(b), "l"(c));
    return d;
}
__device__ __forceinline__ unsigned long long pk2(float v) {   // {v, v}
    unsigned long long r;
    asm("mov.b64 %0, {%1, %1};" : "=l"(r) : "f"(v));
    return r;
}
__device__ __forceinline__ float2 upk(unsigned long long v) {
    float2 f;
    asm("mov.b64 {%0, %1}, %2;" : "=f"(f.x), "=f"(f.y) : "l"(v));
    return f;
}

// ---------------------------------------------------------------------------
// Device scratch (static allocations only — no cudaMalloc allowed)
// ---------------------------------------------------------------------------
__device__ float d_WcT[EE * CC];            // [e][c]  (Wc transposed)
__device__ float d_WihT0[CC * GG];          // [k][g]  forward  Wih^T
__device__ float d_WihT1[CC * GG];          // [k][g]  backward Wih^T
__device__ float d_enc[BB * LL * CC];       // encoder output (b*L+l, c)
__device__ float d_gi0[(long)BB * LL * GG]; // precomputed input gates, fwd
__device__ float d_gi1[(long)BB * LL * GG]; // precomputed input gates, bwd

// ---------------------------------------------------------------------------
// Setup: transpose weights.
// ---------------------------------------------------------------------------
__global__ void k_setup(const float* __restrict__ Wc,
                        const float* __restrict__ Wih_f,
                        const float* __restrict__ Wih_b)
{
    const int i      = blockIdx.x * blockDim.x + threadIdx.x;
    const int stride = gridDim.x * blockDim.x;

    for (int idx = i; idx < EE * CC; idx += stride) {
        int e = idx / CC, c = idx % CC;
        d_WcT[e * CC + c] = Wc[c * EE + e];
    }
    for (int idx = i; idx < CC * GG; idx += stride) {
        int k = idx / GG, g = idx % GG;
        d_WihT0[idx] = Wih_f[g * CC + k];
        d_WihT1[idx] = Wih_b[g * CC + k];
    }
}

// ---------------------------------------------------------------------------
// K1: fused tree encoder. One CTA per (b,l). Inner GEMM in f32x2.
// ---------------------------------------------------------------------------
#define K1_WS 0
#define K1_ES 16896
#define K1_XS 25088
#define K1_BC 33404
#define K1_TK 33532
#define K1_SMEM_FLOATS 33596

__global__ void __launch_bounds__(256) k_tree_encode(const int* __restrict__ tokens,
                                                     const float* __restrict__ emb,
                                                     const float* __restrict__ bc)
{
    extern __shared__ float sm[];
    float* ws  = sm + K1_WS;
    float* es  = sm + K1_ES;
    float* xs  = sm + K1_XS;
    float* bcs = sm + K1_BC;
    int*   tks = (int*)(sm + K1_TK);

    const int bl  = blockIdx.x;
    const int tid = threadIdx.x;

    if (tid < TT) tks[tid] = tokens[bl * TT + tid];
    if (tid < CC) bcs[tid] = bc[tid];

    for (int idx = tid; idx < (EE * CC) / 4; idx += 256) {
        int k  = idx >> 5;
        int c4 = (idx & 31) << 2;
        float4 v = ((const float4*)d_WcT)[idx];
        *(float4*)&ws[k * 132 + c4] = v;
    }
    __syncthreads();

    for (int idx = tid; idx < (64 * EE) / 4; idx += 256) {
        int t  = idx >> 5;
        int c4 = (idx & 31) << 2;
        float4 v = make_float4(0.f, 0.f, 0.f, 0.f);
        if (t < TT) v = *(const float4*)&emb[(long)tks[t] * EE + c4];
        *(float4*)&es[t * 128 + c4] = v;
    }
    __syncthreads();

    const int w    = tid >> 5;
    const int lane = tid & 31;
    const int c4   = lane << 2;

    #pragma unroll
    for (int grp = 0; grp < 2; grp++) {
        const int tbase = w * 8 + grp * 4;
        unsigned long long acc2[4][2];
        #pragma unroll
        for (int n = 0; n < 4; n++) { acc2[n][0] = 0ull; acc2[n][1] = 0ull; }

        for (int k = 0; k < EE; k += 4) {
            float4 e4[4];
            #pragma unroll
            for (int n = 0; n < 4; n++) e4[n] = *(float4*)&es[(tbase + n) * 128 + k];
            #pragma unroll
            for (int kk = 0; kk < 4; kk++) {
                ulonglong2 wu = *(const ulonglong2*)&ws[(k + kk) * 132 + c4];
                #pragma unroll
                for (int n = 0; n < 4; n++) {
                    float ev = (kk == 0) ? e4[n].x : (kk == 1) ? e4[n].y
                             : (kk == 2) ? e4[n].z : e4[n].w;
                    unsigned long long eb = pk2(ev);
                    acc2[n][0] = fma2(eb, wu.x, acc2[n][0]);
                    acc2[n][1] = fma2(eb, wu.y, acc2[n][1]);
                }
            }
        }
        float4 bcv = *(float4*)&bcs[c4];
        #pragma unroll
        for (int n = 0; n < 4; n++) {
            int t = tbase + n;
            if (t < TT) {
                float2 lo = upk(acc2[n][0]);
                float2 hi = upk(acc2[n][1]);
                float4 r;
                r.x = lo.x + bcv.x;
                r.y = lo.y + bcv.y;
                r.z = hi.x + bcv.z;
                r.w = hi.y + bcv.w;
                *(float4*)&xs[t * 132 + c4] = r;
            }
        }
    }
    __syncthreads();

    if (tid < CC) {
        const int c = tid;
        float m = -3.0e38f;
        #pragma unroll
        for (int t = TT - 1; t >= 31; t--) m = fmaxf(m, xs[t * 132 + c]);
        #pragma unroll
        for (int t = 30; t >= 0; t--) {
            float v = xs[t * 132 + c] + xs[(2 * t + 1) * 132 + c] + xs[(2 * t + 2) * 132 + c];
            xs[t * 132 + c] = v;
            m = fmaxf(m, v);
        }
        d_enc[bl * CC + c] = fmaxf(m, 0.f);
    }
}

// ---------------------------------------------------------------------------
// K2: gi[d] = enc @ Wih[d]^T + bih[d]   — f32x2 inner loop
// ---------------------------------------------------------------------------
#define K2_WS 0
#define K2_ES 16896
#define K2_BI 25088
#define K2_SMEM_FLOATS 25216

__global__ void __launch_bounds__(256) k_gi(const float* __restrict__ bih_f,
                                            const float* __restrict__ bih_b)
{
    extern __shared__ float sm[];
    float* ws  = sm + K2_WS;
    float* es  = sm + K2_ES;
    float* bis = sm + K2_BI;

    const int mt = blockIdx.x;
    const int nt = blockIdx.y;
    const int d  = blockIdx.z;
    const int m0 = mt * 64;
    const int g0 = nt * 128;
    const int tid = threadIdx.x;

    const float* WT  = d ? d_WihT1 : d_WihT0;
    const float* bih = d ? bih_b   : bih_f;
    float*       gi  = d ? d_gi1   : d_gi0;

    for (int idx = tid; idx < (128 * 128) / 4; idx += 256) {
        int k  = idx >> 5;
        int j4 = (idx & 31) << 2;
        float4 v = *(const float4*)&WT[k * GG + g0 + j4];
        *(float4*)&ws[k * 132 + j4] = v;
    }
    for (int idx = tid; idx < (64 * 128) / 4; idx += 256) {
        int i  = idx >> 5;
        int k4 = (idx & 31) << 2;
        float4 v = *(const float4*)&d_enc[(m0 + i) * CC + k4];
        *(float4*)&es[i * 128 + k4] = v;
    }
    if (tid < 128) bis[tid] = bih[g0 + tid];
    __syncthreads();

    const int w    = tid >> 5;
    const int lane = tid & 31;
    const int c4   = lane << 2;

    #pragma unroll
    for (int grp = 0; grp < 2; grp++) {
        const int ibase = w * 8 + grp * 4;
        unsigned long long acc2[4][2];
        #pragma unroll
        for (int n = 0; n < 4; n++) { acc2[n][0] = 0ull; acc2[n][1] = 0ull; }

        for (int k = 0; k < CC; k += 4) {
            float4 e4[4];
            #pragma unroll
            for (int n = 0; n < 4; n++) e4[n] = *(float4*)&es[(ibase + n) * 128 + k];
            #pragma unroll
            for (int kk = 0; kk < 4; kk++) {
                ulonglong2 wu = *(const ulonglong2*)&ws[(k + kk) * 132 + c4];
                #pragma unroll
                for (int n = 0; n < 4; n++) {
                    float ev = (kk == 0) ? e4[n].x : (kk == 1) ? e4[n].y
                             : (kk == 2) ? e4[n].z : e4[n].w;
                    unsigned long long eb = pk2(ev);
                    acc2[n][0] = fma2(eb, wu.x, acc2[n][0]);
                    acc2[n][1] = fma2(eb, wu.y, acc2[n][1]);
                }
            }
        }
        float4 bv = *(float4*)&bis[c4];
        #pragma unroll
        for (int n = 0; n < 4; n++) {
            float2 lo = upk(acc2[n][0]);
            float2 hi = upk(acc2[n][1]);
            float4 r;
            r.x = lo.x + bv.x;
            r.y = lo.y + bv.y;
            r.z = hi.x + bv.z;
            r.w = hi.y + bv.w;
            *(float4*)&gi[(long)(m0 + ibase + n) * GG + g0 + c4] = r;
        }
    }
}

// ---------------------------------------------------------------------------
// K3 v3.1: cluster-local bidirectional GRU (structure unchanged from R3),
// dot-product loop converted to f32x2.
// ---------------------------------------------------------------------------
__device__ __forceinline__ uint32_t smem_u32(const void* p) {
    uint32_t a;
    asm("{ .reg .u64 t; cvta.to.shared.u64 t, %1; cvt.u32.u64 %0, t; }"
        : "=r"(a) : "l"(p));
    return a;
}

__device__ __forceinline__ void st_cluster_f32(uint32_t local_addr, uint32_t rank, float v) {
    asm volatile(
        "{\n\t"
        ".reg .b32 r;\n\t"
        "mapa.shared::cluster.u32 r, %0, %1;\n\t"
        "st.shared::cluster.f32 [r], %2;\n\t"
        "}"
        :: "r"(local_addr), "r"(rank), "f"(v) : "memory");
}

__global__ void __launch_bounds__(384, 1) __cluster_dims__(4, 1, 1)
k_gru(const float* __restrict__ Whh_f, const float* __restrict__ bhh_f,
      const float* __restrict__ Whh_b, const float* __restrict__ bhh_b,
      float* __restrict__ out)
{
    __shared__ float hbuf[2][2][HH];   // [buf][bt][unit]
    __shared__ float part[2][192];     // half-1 partial dots [bt][row]
    __shared__ float gates[2][192];    // completed gate pre-activations

    const int tid = threadIdx.x;
    uint32_t cr;
    asm("mov.u32 %0, %%cluster_ctarank;" : "=r"(cr));

    const int cid = blockIdx.x >> 2;
    const int d   = cid >> 4;
    const int bp  = cid & 15;
    const int U0  = (int)cr << 6;

    const float* Whh = d ? Whh_b : Whh_f;
    const float* bhh = d ? bhh_b : bhh_f;
    const float* gi  = d ? d_gi1 : d_gi0;

    const int w    = tid >> 5;
    const int lane = tid & 31;
    const int rw   = (w % 6) * 32 + lane;
    const int half = w / 6;

    const int gate = rw >> 6, uu = rw & 63;
    ulonglong2 wreg[32];
    {
        const float* wrow = &Whh[(gate * HH + U0 + uu) * HH + half * 128];
        #pragma unroll
        for (int i = 0; i < 32; i++) wreg[i] = *(const ulonglong2*)&wrow[i * 4];
    }

    const int u_f   = tid & 63;
    const int bt_f  = tid >> 6;
    const int bglob = bp * 2 + bt_f;
    float br = 0.f, bz = 0.f, bn = 0.f;
    uint32_t haddr0 = 0, haddr1 = 0;
    if (tid < 128) {
        br = bhh[U0 + u_f];
        bz = bhh[HH + U0 + u_f];
        bn = bhh[2 * HH + U0 + u_f];
        haddr0 = smem_u32(&hbuf[0][bt_f][U0 + u_f]);
        haddr1 = smem_u32(&hbuf[1][bt_f][U0 + u_f]);
    }

    for (int i = tid; i < 2 * HH; i += 384) hbuf[0][i >> 8][i & 255] = 0.f;

    float mx = -3.0e38f;

    asm volatile("barrier.cluster.arrive.aligned;" ::: "memory");
    asm volatile("barrier.cluster.wait.aligned;"   ::: "memory");

    for (int st = 0; st < LL; st++) {
        const int p = st & 1;
        const int t = d ? (LL - 1 - st) : st;

        float gir = 0.f, giz = 0.f, gin = 0.f;
        if (tid < 128) {
            const long gb = ((long)bglob * LL + t) * GG + U0 + u_f;
            gir = __ldg(&gi[gb]);
            giz = __ldg(&gi[gb + HH]);
            gin = __ldg(&gi[gb + 2 * HH]);
        }

        // dot products in f32x2: h loads broadcast, weights in registers
        unsigned long long a0a = 0ull, a0b = 0ull, a1a = 0ull, a1b = 0ull;
        {
            const float* h0 = &hbuf[p][0][half * 128];
            const float* h1 = &hbuf[p][1][half * 128];
            #pragma unroll
            for (int i = 0; i < 32; i++) {
                ulonglong2 wv = wreg[i];
                ulonglong2 x0 = *(const ulonglong2*)&h0[i * 4];
                ulonglong2 x1 = *(const ulonglong2*)&h1[i * 4];
                a0a = fma2(wv.x, x0.x, a0a);
                a0b = fma2(wv.y, x0.y, a0b);
                a1a = fma2(wv.x, x1.x, a1a);
                a1b = fma2(wv.y, x1.y, a1b);
            }
        }
        float2 p0a = upk(a0a), p0b = upk(a0b), p1a = upk(a1a), p1b = upk(a1b);
        const float s0 = (p0a.x + p0a.y) + (p0b.x + p0b.y);
        const float s1 = (p1a.x + p1a.y) + (p1b.x + p1b.y);

        if (half == 1) {
            part[0][rw] = s0;
            part[1][rw] = s1;
        }
        __syncthreads();
        if (half == 0) {
            gates[0][rw] = s0 + part[0][rw];
            gates[1][rw] = s1 + part[1][rw];
        }
        __syncthreads();

        if (tid < 128) {
            const float gr = gates[bt_f][u_f];
            const float gz = gates[bt_f][64 + u_f];
            const float gn = gates[bt_f][128 + u_f];
            const float hp = hbuf[p][bt_f][U0 + u_f];

            const float r  = 1.f / (1.f + __expf(-(gir + gr + br)));
            const float z  = 1.f / (1.f + __expf(-(giz + gz + bz)));
            const float nn = tanhf(gin + r * (gn + bn));
            const float hn = (1.f - z) * nn + z * hp;
            mx = fmaxf(mx, hn);

            hbuf[p ^ 1][bt_f][U0 + u_f] = hn;
            const uint32_t ha = (p ^ 1) ? haddr1 : haddr0;
            #pragma unroll
            for (uint32_t rk = 0; rk < 4; rk++) {
                if (rk != cr) st_cluster_f32(ha, rk, hn);
            }
        }

        asm volatile("barrier.cluster.arrive.aligned;" ::: "memory");
        asm volatile("barrier.cluster.wait.aligned;"   ::: "memory");
    }

    if (tid < 128) out[bglob * 512 + d * 256 + U0 + u_f] = mx;
}

// ---------------------------------------------------------------------------
// kernel_launch
// ---------------------------------------------------------------------------
extern "C" void kernel_launch(void* const* d_in, const int* in_sizes, int n_in,
                              void* d_out, int out_size)
{
    const int*   tokens = (const int*)  d_in[0];
    const float* emb    = (const float*)d_in[1];
    const float* Wc     = (const float*)d_in[2];
    const float* bc     = (const float*)d_in[3];
    const float* Wih_f  = (const float*)d_in[4];
    const float* Whh_f  = (const float*)d_in[5];
    const float* bih_f  = (const float*)d_in[6];
    const float* bhh_f  = (const float*)d_in[7];
    const float* Wih_b  = (const float*)d_in[8];
    const float* Whh_b  = (const float*)d_in[9];
    const float* bih_b  = (const float*)d_in[10];
    const float* bhh_b  = (const float*)d_in[11];
    float* out = (float*)d_out;

    const int SM1 = K1_SMEM_FLOATS * 4;
    const int SM2 = K2_SMEM_FLOATS * 4;

    cudaFuncSetAttribute(k_tree_encode, cudaFuncAttributeMaxDynamicSharedMemorySize, SM1);
    cudaFuncSetAttribute(k_gi,          cudaFuncAttributeMaxDynamicSharedMemorySize, SM2);

    k_setup<<<128, 256>>>(Wc, Wih_f, Wih_b);
    k_tree_encode<<<BB * LL, 256, SM1>>>(tokens, emb, bc);
    dim3 g2(64, 6, 2);
    k_gi<<<g2, 256, SM2>>>(bih_f, bih_b);
    k_gru<<<128, 384>>>(Whh_f, bhh_f, Whh_b, bhh_b, out);
}

// round 5
// speedup vs baseline: 2.7406x; 1.3720x over previous
#include <cuda_runtime.h>
#include <cuda_bf16.h>
#include <cstdint>

// Problem constants (fixed by the dataset)
#define BB 32      // batch
#define LL 128     // sequence length
#define TT 63      // tree nodes (2^6 - 1)
#define EE 128     // embedding dim
#define CC 128     // conv/encoder channels
#define HH 256     // GRU hidden
#define GG 768     // 3*H gate columns

// ---------------------------------------------------------------------------
// Packed fp32x2 helpers (Blackwell f32x2 pipe; bitwise-identical fp32 rounding)
// ---------------------------------------------------------------------------
__device__ __forceinline__ unsigned long long fma2(unsigned long long a,
                                                   unsigned long long b,
                                                   unsigned long long c) {
    unsigned long long d;
    asm("fma.rn.f32x2 %0, %1, %2, %3;" : "=l"(d) : "l"(a), "l"(b), "l"(c));
    return d;
}
__device__ __forceinline__ unsigned long long pk2(float v) {   // {v, v}
    unsigned long long r;
    asm("mov.b64 %0, {%1, %1};" : "=l"(r) : "f"(v));
    return r;
}
__device__ __forceinline__ float2 upk(unsigned long long v) {
    float2 f;
    asm("mov.b64 {%0, %1}, %2;" : "=f"(f.x), "=f"(f.y) : "l"(v));
    return f;
}

// ---------------------------------------------------------------------------
// Device scratch (static allocations only — no cudaMalloc allowed)
// ---------------------------------------------------------------------------
__device__ float d_WcT[EE * CC];            // [e][c]  (Wc transposed)
__device__ float d_WihT0[CC * GG];          // [k][g]  forward  Wih^T
__device__ float d_WihT1[CC * GG];          // [k][g]  backward Wih^T
__device__ float d_enc[BB * LL * CC];       // encoder output (b*L+l, c)
__device__ float d_gi0[(long)BB * LL * GG]; // precomputed input gates, fwd
__device__ float d_gi1[(long)BB * LL * GG]; // precomputed input gates, bwd

// ---------------------------------------------------------------------------
// Setup: transpose weights.
// ---------------------------------------------------------------------------
__global__ void k_setup(const float* __restrict__ Wc,
                        const float* __restrict__ Wih_f,
                        const float* __restrict__ Wih_b)
{
    const int i      = blockIdx.x * blockDim.x + threadIdx.x;
    const int stride = gridDim.x * blockDim.x;

    for (int idx = i; idx < EE * CC; idx += stride) {
        int e = idx / CC, c = idx % CC;
        d_WcT[e * CC + c] = Wc[c * EE + e];
    }
    for (int idx = i; idx < CC * GG; idx += stride) {
        int k = idx / GG, g = idx % GG;
        d_WihT0[idx] = Wih_f[g * CC + k];
        d_WihT1[idx] = Wih_b[g * CC + k];
    }
}

// ---------------------------------------------------------------------------
// K1 v2: fused tree encoder. One CTA per (b,l), 256 threads, 2 CTAs/SM.
//  - warp w computes ALL 8 nodes [8w, 8w+8) in one pass (2x W reuse per load)
//  - node values written IN-PLACE into the embedding tile (each row is
//    private to its owning warp), saving 33KB smem
//  - unpadded stride 128 (float4 row access is conflict-free)
// Shared (floats): ws[128*128] @0, es[64*128] @16384 (doubles as node buf),
//                  bcs[128] @24576, tks[64] @24704
// ---------------------------------------------------------------------------
#define K1_WS 0
#define K1_ES 16384
#define K1_BC 24576
#define K1_TK 24704
#define K1_SMEM_FLOATS 24768

__global__ void __launch_bounds__(256) k_tree_encode(const int* __restrict__ tokens,
                                                     const float* __restrict__ emb,
                                                     const float* __restrict__ bc)
{
    extern __shared__ float sm[];
    float* ws  = sm + K1_WS;
    float* es  = sm + K1_ES;
    float* bcs = sm + K1_BC;
    int*   tks = (int*)(sm + K1_TK);

    const int bl  = blockIdx.x;
    const int tid = threadIdx.x;

    if (tid < TT) tks[tid] = tokens[bl * TT + tid];
    if (tid < CC) bcs[tid] = bc[tid];

    for (int idx = tid; idx < (EE * CC) / 4; idx += 256)
        ((float4*)ws)[idx] = ((const float4*)d_WcT)[idx];
    __syncthreads();   // tks ready

    for (int idx = tid; idx < (64 * EE) / 4; idx += 256) {
        int t  = idx >> 5;
        int c4 = (idx & 31) << 2;
        float4 v = make_float4(0.f, 0.f, 0.f, 0.f);
        if (t < TT) v = *(const float4*)&emb[(long)tks[t] * EE + c4];
        *(float4*)&es[t * 128 + c4] = v;
    }
    __syncthreads();

    const int w     = tid >> 5;
    const int lane  = tid & 31;
    const int c4    = lane << 2;
    const int tbase = w * 8;

    unsigned long long acc2[8][2];
    #pragma unroll
    for (int n = 0; n < 8; n++) { acc2[n][0] = 0ull; acc2[n][1] = 0ull; }

    for (int k = 0; k < EE; k += 4) {
        float4 e4[8];
        #pragma unroll
        for (int n = 0; n < 8; n++) e4[n] = *(float4*)&es[(tbase + n) * 128 + k];
        #pragma unroll
        for (int kk = 0; kk < 4; kk++) {
            ulonglong2 wu = *(const ulonglong2*)&ws[(k + kk) * 128 + c4];
            #pragma unroll
            for (int n = 0; n < 8; n++) {
                float ev = (kk == 0) ? e4[n].x : (kk == 1) ? e4[n].y
                         : (kk == 2) ? e4[n].z : e4[n].w;
                unsigned long long eb = pk2(ev);
                acc2[n][0] = fma2(eb, wu.x, acc2[n][0]);
                acc2[n][1] = fma2(eb, wu.y, acc2[n][1]);
            }
        }
    }

    // in-place store: this warp owns rows [tbase, tbase+8); all its reads done
    {
        float4 bcv = *(float4*)&bcs[c4];
        #pragma unroll
        for (int n = 0; n < 8; n++) {
            int t = tbase + n;
            if (t < TT) {
                float2 lo = upk(acc2[n][0]);
                float2 hi = upk(acc2[n][1]);
                float4 r;
                r.x = lo.x + bcv.x;
                r.y = lo.y + bcv.y;
                r.z = hi.x + bcv.z;
                r.w = hi.y + bcv.w;
                *(float4*)&es[t * 128 + c4] = r;
            }
        }
    }
    __syncthreads();

    // heap accumulation + max + relu (per-channel)
    if (tid < CC) {
        const int c = tid;
        float m = -3.0e38f;
        #pragma unroll
        for (int t = TT - 1; t >= 31; t--) m = fmaxf(m, es[t * 128 + c]);
        #pragma unroll
        for (int t = 30; t >= 0; t--) {
            float v = es[t * 128 + c] + es[(2 * t + 1) * 128 + c] + es[(2 * t + 2) * 128 + c];
            es[t * 128 + c] = v;
            m = fmaxf(m, v);
        }
        d_enc[bl * CC + c] = fmaxf(m, 0.f);
    }
}

// ---------------------------------------------------------------------------
// K2 v2: gi[d] = enc @ Wih[d]^T + bih[d] — 8-row register blocking, unpadded.
// Shared: ws[128*128] @0, es[64*128] @16384, bis[128] @24576
// ---------------------------------------------------------------------------
#define K2_WS 0
#define K2_ES 16384
#define K2_BI 24576
#define K2_SMEM_FLOATS 24704

__global__ void __launch_bounds__(256) k_gi(const float* __restrict__ bih_f,
                                            const float* __restrict__ bih_b)
{
    extern __shared__ float sm[];
    float* ws  = sm + K2_WS;
    float* es  = sm + K2_ES;
    float* bis = sm + K2_BI;

    const int mt = blockIdx.x;
    const int nt = blockIdx.y;
    const int d  = blockIdx.z;
    const int m0 = mt * 64;
    const int g0 = nt * 128;
    const int tid = threadIdx.x;

    const float* WT  = d ? d_WihT1 : d_WihT0;
    const float* bih = d ? bih_b   : bih_f;
    float*       gi  = d ? d_gi1   : d_gi0;

    for (int idx = tid; idx < (128 * 128) / 4; idx += 256) {
        int k  = idx >> 5;
        int j4 = (idx & 31) << 2;
        float4 v = *(const float4*)&WT[k * GG + g0 + j4];
        *(float4*)&ws[k * 128 + j4] = v;
    }
    for (int idx = tid; idx < (64 * 128) / 4; idx += 256) {
        int i  = idx >> 5;
        int k4 = (idx & 31) << 2;
        float4 v = *(const float4*)&d_enc[(m0 + i) * CC + k4];
        *(float4*)&es[i * 128 + k4] = v;
    }
    if (tid < 128) bis[tid] = bih[g0 + tid];
    __syncthreads();

    const int w     = tid >> 5;
    const int lane  = tid & 31;
    const int c4    = lane << 2;
    const int ibase = w * 8;

    unsigned long long acc2[8][2];
    #pragma unroll
    for (int n = 0; n < 8; n++) { acc2[n][0] = 0ull; acc2[n][1] = 0ull; }

    for (int k = 0; k < CC; k += 4) {
        float4 e4[8];
        #pragma unroll
        for (int n = 0; n < 8; n++) e4[n] = *(float4*)&es[(ibase + n) * 128 + k];
        #pragma unroll
        for (int kk = 0; kk < 4; kk++) {
            ulonglong2 wu = *(const ulonglong2*)&ws[(k + kk) * 128 + c4];
            #pragma unroll
            for (int n = 0; n < 8; n++) {
                float ev = (kk == 0) ? e4[n].x : (kk == 1) ? e4[n].y
                         : (kk == 2) ? e4[n].z : e4[n].w;
                unsigned long long eb = pk2(ev);
                acc2[n][0] = fma2(eb, wu.x, acc2[n][0]);
                acc2[n][1] = fma2(eb, wu.y, acc2[n][1]);
            }
        }
    }

    float4 bv = *(float4*)&bis[c4];
    #pragma unroll
    for (int n = 0; n < 8; n++) {
        float2 lo = upk(acc2[n][0]);
        float2 hi = upk(acc2[n][1]);
        float4 r;
        r.x = lo.x + bv.x;
        r.y = lo.y + bv.y;
        r.z = hi.x + bv.z;
        r.w = hi.y + bv.w;
        *(float4*)&gi[(long)(m0 + ibase + n) * GG + g0 + c4] = r;
    }
}

// ---------------------------------------------------------------------------
// K3 v4: cluster-local bidirectional GRU (R3 float4 dot loop restored),
// single-sync split reduction: both halves publish partials, finalize
// threads sum the two halves directly (no 'gates' pass, one less sync).
// ---------------------------------------------------------------------------
__device__ __forceinline__ uint32_t smem_u32(const void* p) {
    uint32_t a;
    asm("{ .reg .u64 t; cvta.to.shared.u64 t, %1; cvt.u32.u64 %0, t; }"
        : "=r"(a) : "l"(p));
    return a;
}

__device__ __forceinline__ void st_cluster_f32(uint32_t local_addr, uint32_t rank, float v) {
    asm volatile(
        "{\n\t"
        ".reg .b32 r;\n\t"
        "mapa.shared::cluster.u32 r, %0, %1;\n\t"
        "st.shared::cluster.f32 [r], %2;\n\t"
        "}"
        :: "r"(local_addr), "r"(rank), "f"(v) : "memory");
}

__global__ void __launch_bounds__(384, 1) __cluster_dims__(4, 1, 1)
k_gru(const float* __restrict__ Whh_f, const float* __restrict__ bhh_f,
      const float* __restrict__ Whh_b, const float* __restrict__ bhh_b,
      float* __restrict__ out)
{
    __shared__ float hbuf[2][2][HH];     // [buf][bt][unit]
    __shared__ float part[2][2][192];    // [half][bt][row] partial dots

    const int tid = threadIdx.x;
    uint32_t cr;
    asm("mov.u32 %0, %%cluster_ctarank;" : "=r"(cr));

    const int cid = blockIdx.x >> 2;
    const int d   = cid >> 4;
    const int bp  = cid & 15;
    const int U0  = (int)cr << 6;

    const float* Whh = d ? Whh_b : Whh_f;
    const float* bhh = d ? bhh_b : bhh_f;
    const float* gi  = d ? d_gi1 : d_gi0;

    const int w    = tid >> 5;
    const int lane = tid & 31;
    const int rw   = (w % 6) * 32 + lane;  // 0..191  (gate*64 + u)
    const int half = w / 6;                // 0 or 1

    const int gate = rw >> 6, uu = rw & 63;
    float4 wreg[32];
    {
        const float* wrow = &Whh[(gate * HH + U0 + uu) * HH + half * 128];
        #pragma unroll
        for (int i = 0; i < 32; i++) wreg[i] = *(const float4*)&wrow[i * 4];
    }

    const int u_f   = tid & 63;
    const int bt_f  = tid >> 6;
    const int bglob = bp * 2 + bt_f;
    float br = 0.f, bz = 0.f, bn = 0.f;
    uint32_t haddr0 = 0, haddr1 = 0;
    if (tid < 128) {
        br = bhh[U0 + u_f];
        bz = bhh[HH + U0 + u_f];
        bn = bhh[2 * HH + U0 + u_f];
        haddr0 = smem_u32(&hbuf[0][bt_f][U0 + u_f]);
        haddr1 = smem_u32(&hbuf[1][bt_f][U0 + u_f]);
    }

    for (int i = tid; i < 2 * HH; i += 384) hbuf[0][i >> 8][i & 255] = 0.f;

    float mx = -3.0e38f;

    asm volatile("barrier.cluster.arrive.aligned;" ::: "memory");
    asm volatile("barrier.cluster.wait.aligned;"   ::: "memory");

    for (int st = 0; st < LL; st++) {
        const int p = st & 1;
        const int t = d ? (LL - 1 - st) : st;

        // gi loads issue early; consumed ~1.5K cycles later at finalize
        float gir = 0.f, giz = 0.f, gin = 0.f;
        if (tid < 128) {
            const long gb = ((long)bglob * LL + t) * GG + U0 + u_f;
            gir = __ldg(&gi[gb]);
            giz = __ldg(&gi[gb + HH]);
            gin = __ldg(&gi[gb + 2 * HH]);
        }

        // dot products: h loads are warp-broadcast LDS, weights in registers
        float4 a0 = make_float4(0.f, 0.f, 0.f, 0.f);
        float4 a1 = make_float4(0.f, 0.f, 0.f, 0.f);
        {
            const float* h0 = &hbuf[p][0][half * 128];
            const float* h1 = &hbuf[p][1][half * 128];
            #pragma unroll
            for (int i = 0; i < 32; i++) {
                float4 wv = wreg[i];
                float4 x0 = *(const float4*)&h0[i * 4];
                float4 x1 = *(const float4*)&h1[i * 4];
                a0.x += wv.x * x0.x; a0.y += wv.y * x0.y;
                a0.z += wv.z * x0.z; a0.w += wv.w * x0.w;
                a1.x += wv.x * x1.x; a1.y += wv.y * x1.y;
                a1.z += wv.z * x1.z; a1.w += wv.w * x1.w;
            }
        }
        const float s0 = (a0.x + a0.y) + (a0.z + a0.w);
        const float s1 = (a1.x + a1.y) + (a1.z + a1.w);

        part[half][0][rw] = s0;
        part[half][1][rw] = s1;
        __syncthreads();

        // finalize: sum the two halves, GRU nonlinearity, push h to peers
        if (tid < 128) {
            const float gr = part[0][bt_f][u_f]       + part[1][bt_f][u_f];
            const float gz = part[0][bt_f][64 + u_f]  + part[1][bt_f][64 + u_f];
            const float gn = part[0][bt_f][128 + u_f] + part[1][bt_f][128 + u_f];
            const float hp = hbuf[p][bt_f][U0 + u_f];

            const float r  = 1.f / (1.f + __expf(-(gir + gr + br)));
            const float z  = 1.f / (1.f + __expf(-(giz + gz + bz)));
            const float nn = tanhf(gin + r * (gn + bn));
            const float hn = (1.f - z) * nn + z * hp;
            mx = fmaxf(mx, hn);

            hbuf[p ^ 1][bt_f][U0 + u_f] = hn;
            const uint32_t ha = (p ^ 1) ? haddr1 : haddr0;
            #pragma unroll
            for (uint32_t rk = 0; rk < 4; rk++) {
                if (rk != cr) st_cluster_f32(ha, rk, hn);
            }
        }

        // step boundary: DSMEM writes visible cluster-wide after this
        asm volatile("barrier.cluster.arrive.aligned;" ::: "memory");
        asm volatile("barrier.cluster.wait.aligned;"   ::: "memory");
    }

    if (tid < 128) out[bglob * 512 + d * 256 + U0 + u_f] = mx;
}

// ---------------------------------------------------------------------------
// kernel_launch
// ---------------------------------------------------------------------------
extern "C" void kernel_launch(void* const* d_in, const int* in_sizes, int n_in,
                              void* d_out, int out_size)
{
    const int*   tokens = (const int*)  d_in[0];
    const float* emb    = (const float*)d_in[1];
    const float* Wc     = (const float*)d_in[2];
    const float* bc     = (const float*)d_in[3];
    const float* Wih_f  = (const float*)d_in[4];
    const float* Whh_f  = (const float*)d_in[5];
    const float* bih_f  = (const float*)d_in[6];
    const float* bhh_f  = (const float*)d_in[7];
    const float* Wih_b  = (const float*)d_in[8];
    const float* Whh_b  = (const float*)d_in[9];
    const float* bih_b  = (const float*)d_in[10];
    const float* bhh_b  = (const float*)d_in[11];
    float* out = (float*)d_out;

    const int SM1 = K1_SMEM_FLOATS * 4;
    const int SM2 = K2_SMEM_FLOATS * 4;

    cudaFuncSetAttribute(k_tree_encode, cudaFuncAttributeMaxDynamicSharedMemorySize, SM1);
    cudaFuncSetAttribute(k_gi,          cudaFuncAttributeMaxDynamicSharedMemorySize, SM2);

    k_setup<<<128, 256>>>(Wc, Wih_f, Wih_b);
    k_tree_encode<<<BB * LL, 256, SM1>>>(tokens, emb, bc);
    dim3 g2(64, 6, 2);
    k_gi<<<g2, 256, SM2>>>(bih_f, bih_b);
    k_gru<<<128, 384>>>(Whh_f, bhh_f, Whh_b, bhh_b, out);
}